// round 4
// baseline (speedup 1.0000x reference)
#include <cuda_runtime.h>
#include <cstdint>

// Problem constants (fixed shapes)
#define BB 4096
#define SS 2048
#define INW 8
#define HH 8

__device__ int g_hist[SS];
__device__ int g_off[SS];
__device__ int g_perm[BB];

// ---------------- activation helpers (flag-independent, accurate approx) --------------
__device__ __forceinline__ float ex2f_(float x) {
    float r; asm("ex2.approx.f32 %0, %1;" : "=f"(r) : "f"(x)); return r;
}
__device__ __forceinline__ float rcpf_(float x) {
    float r; asm("rcp.approx.f32 %0, %1;" : "=f"(r) : "f"(x)); return r;
}
__device__ __forceinline__ float sigmoidf_(float x) {
    // 1/(1+2^(-x*log2e))
    return rcpf_(1.0f + ex2f_(-1.4426950408889634f * x));
}
__device__ __forceinline__ float tanhf_(float x) {
    // 2/(1+2^(-2x*log2e)) - 1
    return fmaf(2.0f, rcpf_(1.0f + ex2f_(-2.8853900817779268f * x)), -1.0f);
}

// ---------------- counting sort by length, descending ----------------
__global__ void k_zero() {
    int i = blockIdx.x * blockDim.x + threadIdx.x;
    if (i < SS) g_hist[i] = 0;
}
__global__ void k_hist(const int* __restrict__ lengths) {
    int b = blockIdx.x * blockDim.x + threadIdx.x;
    if (b < BB) {
        int key = SS - lengths[b];   // len in [1,SS] -> key in [0,SS-1], 0 = longest
        atomicAdd(&g_hist[key], 1);
    }
}
__global__ void k_scan() {
    // one block, 1024 threads, 2048 elements, double-buffered Hillis-Steele
    __shared__ int shA[SS];
    __shared__ int shB[SS];
    int t = threadIdx.x;
    shA[t] = g_hist[t];
    shA[t + 1024] = g_hist[t + 1024];
    __syncthreads();
    int* src = shA;
    int* dst = shB;
    for (int off = 1; off < SS; off <<= 1) {
        for (int i = t; i < SS; i += 1024) {
            int v = src[i];
            if (i >= off) v += src[i - off];
            dst[i] = v;
        }
        __syncthreads();
        int* tmp = src; src = dst; dst = tmp;
    }
    for (int i = t; i < SS; i += 1024) {
        g_off[i] = (i == 0) ? 0 : src[i - 1];
    }
}
__global__ void k_scatter(const int* __restrict__ lengths) {
    int b = blockIdx.x * blockDim.x + threadIdx.x;
    if (b < BB) {
        int key = SS - lengths[b];
        int p = atomicAdd(&g_off[key], 1);
        g_perm[p] = b;
    }
}

// ---------------- main LSTM kernel ----------------
// 16 lanes per sequence, 2 sequences per warp. 2048 warps, 256 blocks x 256 threads.
// lane s in [0,16): m = s&7, half A (s<8) owns gate rows m (i) and m+8 (f),
//                   half B (s>=8) owns rows m+16 (g) and m+24 (o).
// h0/h1 live on half-B lanes (lane base+8+m holds h_m); c0/c1 live on half-A lanes.
__global__ __launch_bounds__(256)
void lstm_ac_kernel(const float* __restrict__ seq,
                    const int*   __restrict__ lengths,
                    const float* __restrict__ Wih0, const float* __restrict__ Whh0,
                    const float* __restrict__ bih0, const float* __restrict__ bhh0,
                    const float* __restrict__ Wih1, const float* __restrict__ Whh1,
                    const float* __restrict__ bih1, const float* __restrict__ bhh1,
                    const float* __restrict__ Wl,  const float* __restrict__ bl,
                    const float* __restrict__ Wv,  const float* __restrict__ bv,
                    const float* __restrict__ Wa,  const float* __restrict__ ba,
                    const float* __restrict__ log_std,
                    float* __restrict__ out)
{
    const unsigned FULL = 0xffffffffu;
    int lane = threadIdx.x & 31;
    int wib  = threadIdx.x >> 5;                 // warp in block (0..7)
    int pair = blockIdx.x + wib * 256;           // stride pairs across blocks for SM balance
    int grp  = lane >> 4;                        // 0 or 1
    int s    = lane & 15;
    int m    = s & 7;
    int hB   = s >> 3;                           // 0 = half A, 1 = half B
    int base = grp << 4;

    int b   = g_perm[2 * pair + grp];
    int len = lengths[b];
    int lenA = __shfl_sync(FULL, len, 0);
    int lenB = __shfl_sync(FULL, len, 16);
    int wmax = lenA > lenB ? lenA : lenB;

    // gate rows owned by this lane
    int r0 = m + (hB ? 16 : 0);   // i (A) or g (B)
    int r1 = m + (hB ? 24 : 8);   // f (A) or o (B)

    // register-resident weights
    float w0a[8], w0b[8], w0ha[8], w0hb[8];
    float w1a[8], w1b[8], w1ha[8], w1hb[8];
#pragma unroll
    for (int k = 0; k < 8; k++) {
        w0a[k]  = Wih0[r0 * 8 + k];  w0b[k]  = Wih0[r1 * 8 + k];
        w0ha[k] = Whh0[r0 * 8 + k];  w0hb[k] = Whh0[r1 * 8 + k];
        w1a[k]  = Wih1[r0 * 8 + k];  w1b[k]  = Wih1[r1 * 8 + k];
        w1ha[k] = Whh1[r0 * 8 + k];  w1hb[k] = Whh1[r1 * 8 + k];
    }
    float bias00 = bih0[r0] + bhh0[r0];
    float bias01 = bih0[r1] + bhh0[r1];
    float bias10 = bih1[r0] + bhh1[r0];
    float bias11 = bih1[r1] + bhh1[r1];

    // unified activation constants: half A -> sigmoid, half B -> tanh for row r0
    const float k1 = hB ? -2.8853900817779268f : -1.4426950408889634f;
    const float k2 = hB ? 2.0f : 1.0f;
    const float k3 = hB ? -1.0f : 0.0f;
    const float KS = -1.4426950408889634f;   // sigmoid exponent scale for row r1

    float c0v = 0.f, c1v = 0.f, h0v = 0.f, h1v = 0.f, yv = 0.f;

    const float* xptr = seq + (size_t)b * SS * INW + m;
    float xv = xptr[0];

    for (int t = 0; t < wmax; t++) {
        int tn = (t + 1 < SS) ? (t + 1) : (SS - 1);
        float xn = xptr[(size_t)tn * INW];     // prefetch next timestep

        // ---- layer 0 ----
        float a0 = bias00, a1 = bias01;
#pragma unroll
        for (int k = 0; k < 8; k++) {
            float vk = __shfl_sync(FULL, xv, base + k);      // x held on half A lanes
            a0 = fmaf(w0a[k], vk, a0);
            a1 = fmaf(w0b[k], vk, a1);
        }
#pragma unroll
        for (int k = 0; k < 8; k++) {
            float hk = __shfl_sync(FULL, h0v, base + 8 + k); // h0 held on half B lanes
            a0 = fmaf(w0ha[k], hk, a0);
            a1 = fmaf(w0hb[k], hk, a1);
        }
        float rA = fmaf(k2, rcpf_(1.0f + ex2f_(a0 * k1)), k3);   // i (A) / g (B)
        float rB = rcpf_(1.0f + ex2f_(a1 * KS));                 // f (A) / o (B)
        float gsh = __shfl_sync(FULL, rA, base + 8 + m);         // tanh(g_m) to half A
        c0v = fmaf(rB, c0v, rA * gsh);                           // valid on half A
        float tc = tanhf_(c0v);
        float tcs = __shfl_sync(FULL, tc, base + m);             // tanh(c_m) to half B
        h0v = rB * tcs;                                          // o * tanh(c), valid on half B

        // ---- layer 1 (input = h0, recurrent = h1; both on half B lanes) ----
        float b0 = bias10, b1 = bias11;
#pragma unroll
        for (int k = 0; k < 8; k++) {
            float vk = __shfl_sync(FULL, h0v, base + 8 + k);
            b0 = fmaf(w1a[k], vk, b0);
            b1 = fmaf(w1b[k], vk, b1);
        }
#pragma unroll
        for (int k = 0; k < 8; k++) {
            float hk = __shfl_sync(FULL, h1v, base + 8 + k);
            b0 = fmaf(w1ha[k], hk, b0);
            b1 = fmaf(w1hb[k], hk, b1);
        }
        float sA = fmaf(k2, rcpf_(1.0f + ex2f_(b0 * k1)), k3);
        float sB = rcpf_(1.0f + ex2f_(b1 * KS));
        float gsh1 = __shfl_sync(FULL, sA, base + 8 + m);
        c1v = fmaf(sB, c1v, sA * gsh1);
        float tc1 = tanhf_(c1v);
        float tcs1 = __shfl_sync(FULL, tc1, base + m);
        h1v = sB * tcs1;                                         // valid on half B

        yv = (t == len - 1) ? h1v : yv;                          // snapshot final h1
        xv = xn;
    }

    // ---- heads (once per sequence) ----
    float y[8];
#pragma unroll
    for (int k = 0; k < 8; k++) y[k] = __shfl_sync(FULL, yv, base + 8 + k);

    if (s == 0) {
        float feat[4];
#pragma unroll
        for (int j = 0; j < 4; j++) {
            float a = bl[j];
#pragma unroll
            for (int k = 0; k < 8; k++) a = fmaf(Wl[j * 8 + k], y[k], a);
            feat[j] = tanhf_(a);
        }
        float val = bv[0];
#pragma unroll
        for (int j = 0; j < 4; j++) val = fmaf(Wv[j], feat[j], val);
        out[b] = val;
#pragma unroll
        for (int a = 0; a < 4; a++) {
            float mv = ba[a];
#pragma unroll
            for (int j = 0; j < 4; j++) mv = fmaf(Wa[a * 4 + j], feat[j], mv);
            float ls = log_std[a];
            out[BB + b * 4 + a]          = mv;                        // action_mean
            out[BB + 4 * BB + b * 4 + a] = ls;                        // action_log_std
            out[BB + 8 * BB + b * 4 + a] = ex2f_(ls * 1.4426950408889634f); // action_std
        }
    }
}

extern "C" void kernel_launch(void* const* d_in, const int* in_sizes, int n_in,
                              void* d_out, int out_size)
{
    const float* seq     = (const float*)d_in[0];
    const int*   lengths = (const int*)  d_in[1];
    const float* Wih0 = (const float*)d_in[2];
    const float* Whh0 = (const float*)d_in[3];
    const float* bih0 = (const float*)d_in[4];
    const float* bhh0 = (const float*)d_in[5];
    const float* Wih1 = (const float*)d_in[6];
    const float* Whh1 = (const float*)d_in[7];
    const float* bih1 = (const float*)d_in[8];
    const float* bhh1 = (const float*)d_in[9];
    const float* Wl   = (const float*)d_in[10];
    const float* bl   = (const float*)d_in[11];
    const float* Wv   = (const float*)d_in[12];
    const float* bv   = (const float*)d_in[13];
    const float* Wa   = (const float*)d_in[14];
    const float* ba   = (const float*)d_in[15];
    const float* log_std = (const float*)d_in[16];
    float* out = (float*)d_out;

    // length-descending counting sort -> g_perm
    k_zero<<<(SS + 1023) / 1024, 1024>>>();
    k_hist<<<(BB + 255) / 256, 256>>>(lengths);
    k_scan<<<1, 1024>>>();
    k_scatter<<<(BB + 255) / 256, 256>>>(lengths);

    // main: 2048 warps (2 seqs each), 256 blocks x 256 threads
    lstm_ac_kernel<<<256, 256>>>(seq, lengths,
                                 Wih0, Whh0, bih0, bhh0,
                                 Wih1, Whh1, bih1, bhh1,
                                 Wl, bl, Wv, bv, Wa, ba, log_std,
                                 out);
}

// round 6
// speedup vs baseline: 1.0942x; 1.0942x over previous
#include <cuda_runtime.h>
#include <cstdint>

// Problem constants (fixed shapes)
#define BB 4096
#define SS 2048
#define INW 8
#define HH 8

typedef unsigned long long u64;

__device__ int g_hist[SS];
__device__ int g_off[SS];
__device__ int g_perm[BB];

// ---------------- scalar helpers --------------
__device__ __forceinline__ float ex2f_(float x) {
    float r; asm("ex2.approx.f32 %0, %1;" : "=f"(r) : "f"(x)); return r;
}
__device__ __forceinline__ float rcpf_(float x) {
    float r; asm("rcp.approx.f32 %0, %1;" : "=f"(r) : "f"(x)); return r;
}
__device__ __forceinline__ float tanhf_(float x) {
    return fmaf(2.0f, rcpf_(1.0f + ex2f_(-2.8853900817779268f * x)), -1.0f);
}

// ---------------- packed f32x2 helpers (sm_103a) --------------
__device__ __forceinline__ u64 pk2(float lo, float hi) {
    u64 r; asm("mov.b64 %0, {%1, %2};" : "=l"(r) : "f"(lo), "f"(hi)); return r;
}
__device__ __forceinline__ void unpk2(u64 v, float& lo, float& hi) {
    asm("mov.b64 {%0, %1}, %2;" : "=f"(lo), "=f"(hi) : "l"(v));
}
__device__ __forceinline__ u64 ffma2(u64 a, u64 b, u64 c) {
    u64 d; asm("fma.rn.f32x2 %0, %1, %2, %3;" : "=l"(d) : "l"(a), "l"(b), "l"(c)); return d;
}
__device__ __forceinline__ float hsum2(u64 v) {
    float lo, hi; unpk2(v, lo, hi); return lo + hi;
}

// ---------------- counting sort by length, descending ----------------
__global__ void k_zero() {
    int i = blockIdx.x * blockDim.x + threadIdx.x;
    if (i < SS) g_hist[i] = 0;
}
__global__ void k_hist(const int* __restrict__ lengths) {
    int b = blockIdx.x * blockDim.x + threadIdx.x;
    if (b < BB) {
        int key = SS - lengths[b];
        atomicAdd(&g_hist[key], 1);
    }
}
__global__ void k_scan() {
    __shared__ int shA[SS];
    __shared__ int shB[SS];
    int t = threadIdx.x;
    shA[t] = g_hist[t];
    shA[t + 1024] = g_hist[t + 1024];
    __syncthreads();
    int* src = shA;
    int* dst = shB;
    for (int off = 1; off < SS; off <<= 1) {
        for (int i = t; i < SS; i += 1024) {
            int v = src[i];
            if (i >= off) v += src[i - off];
            dst[i] = v;
        }
        __syncthreads();
        int* tmp = src; src = dst; dst = tmp;
    }
    for (int i = t; i < SS; i += 1024) {
        g_off[i] = (i == 0) ? 0 : src[i - 1];
    }
}
__global__ void k_scatter(const int* __restrict__ lengths) {
    int b = blockIdx.x * blockDim.x + threadIdx.x;
    if (b < BB) {
        int key = SS - lengths[b];
        int p = atomicAdd(&g_off[key], 1);
        g_perm[p] = b;
    }
}

// ---------------- main LSTM kernel ----------------
// 16 lanes per sequence, 2 sequences per warp. 2048 warps, 256 blocks x 256 threads.
// lane s in [0,16): m = s&7; half A (s<8) owns gate rows m (i) and m+8 (f),
//                   half B (s>=8) owns rows m+16 (g) and m+24 (o).
// Every lane keeps full h0[8] / h1[8] register-replicated (as 4 packed f32x2),
// refreshed once per layer through a 32B smem staging slot.
__global__ __launch_bounds__(256)
void lstm_ac_kernel(const float* __restrict__ seq,
                    const int*   __restrict__ lengths,
                    const float* __restrict__ Wih0, const float* __restrict__ Whh0,
                    const float* __restrict__ bih0, const float* __restrict__ bhh0,
                    const float* __restrict__ Wih1, const float* __restrict__ Whh1,
                    const float* __restrict__ bih1, const float* __restrict__ bhh1,
                    const float* __restrict__ Wl,  const float* __restrict__ bl,
                    const float* __restrict__ Wv,  const float* __restrict__ bv,
                    const float* __restrict__ Wa,  const float* __restrict__ ba,
                    const float* __restrict__ log_std,
                    float* __restrict__ out)
{
    __shared__ __align__(16) float hx[8][2][2][8];   // [warp][grp][h0/h1][m]

    const unsigned FULL = 0xffffffffu;
    int lane = threadIdx.x & 31;
    int wib  = threadIdx.x >> 5;
    int pair = blockIdx.x + wib * 256;          // stride pairs across blocks
    int grp  = lane >> 4;
    int s    = lane & 15;
    int m    = s & 7;
    int hB   = s >> 3;
    int base = grp << 4;

    int b   = g_perm[2 * pair + grp];
    int len = lengths[b];
    int lo  = __shfl_sync(FULL, len, lane ^ 16);
    int wmax = len > lo ? len : lo;

    int r0 = m + (hB ? 16 : 0);   // i (A) or g (B)
    int r1 = m + (hB ? 24 : 8);   // f (A) or o (B)

    // activation prescale folded into weights+biases:
    // row r0: sigmoid (A) needs -log2e ; tanh (B) needs -2*log2e. row r1: sigmoid.
    const float sc0 = hB ? -2.8853900817779268f : -1.4426950408889634f;
    const float sc1 = -1.4426950408889634f;
    const float k2 = hB ? 2.0f : 1.0f;
    const float k3 = hB ? -1.0f : 0.0f;

    // packed prescaled weights: 8 vectors of 4 x f32x2
    u64 w0a[4], w0b[4], w0ha[4], w0hb[4];
    u64 w1a[4], w1b[4], w1ha[4], w1hb[4];
#pragma unroll
    for (int j = 0; j < 4; j++) {
        w0a[j]  = pk2(Wih0[r0*8+2*j]*sc0, Wih0[r0*8+2*j+1]*sc0);
        w0b[j]  = pk2(Wih0[r1*8+2*j]*sc1, Wih0[r1*8+2*j+1]*sc1);
        w0ha[j] = pk2(Whh0[r0*8+2*j]*sc0, Whh0[r0*8+2*j+1]*sc0);
        w0hb[j] = pk2(Whh0[r1*8+2*j]*sc1, Whh0[r1*8+2*j+1]*sc1);
        w1a[j]  = pk2(Wih1[r0*8+2*j]*sc0, Wih1[r0*8+2*j+1]*sc0);
        w1b[j]  = pk2(Wih1[r1*8+2*j]*sc1, Wih1[r1*8+2*j+1]*sc1);
        w1ha[j] = pk2(Whh1[r0*8+2*j]*sc0, Whh1[r0*8+2*j+1]*sc0);
        w1hb[j] = pk2(Whh1[r1*8+2*j]*sc1, Whh1[r1*8+2*j+1]*sc1);
    }
    const float b00 = (bih0[r0] + bhh0[r0]) * sc0;
    const float b01 = (bih0[r1] + bhh0[r1]) * sc1;
    const float b10 = (bih1[r0] + bhh1[r0]) * sc0;
    const float b11 = (bih1[r1] + bhh1[r1]) * sc1;

    u64 h0p[4] = {0,0,0,0};
    u64 h1p[4] = {0,0,0,0};
    u64 yp[4]  = {0,0,0,0};
    float c0v = 0.f, c1v = 0.f;

    // x row: 8 floats = 32B per step, 32B-aligned -> 2 x ulonglong2 per step
    const ulonglong2* xrow = (const ulonglong2*)(seq + (size_t)b * SS * INW);
    ulonglong2 xc = xrow[0];
    ulonglong2 xd = xrow[1];

    for (int t = 0; t < wmax; t++) {
        int tn = (t + 1 < SS) ? (t + 1) : (SS - 1);
        ulonglong2 xcn = xrow[2 * tn];         // prefetch next step's x
        ulonglong2 xdn = xrow[2 * tn + 1];

        // ---- layer 0 ----
        u64 A0 = pk2(b00, 0.f), A1 = pk2(b01, 0.f);
        A0 = ffma2(w0a[0], xc.x, A0);  A1 = ffma2(w0b[0], xc.x, A1);
        A0 = ffma2(w0a[1], xc.y, A0);  A1 = ffma2(w0b[1], xc.y, A1);
        A0 = ffma2(w0a[2], xd.x, A0);  A1 = ffma2(w0b[2], xd.x, A1);
        A0 = ffma2(w0a[3], xd.y, A0);  A1 = ffma2(w0b[3], xd.y, A1);
#pragma unroll
        for (int j = 0; j < 4; j++) {
            A0 = ffma2(w0ha[j], h0p[j], A0);
            A1 = ffma2(w0hb[j], h0p[j], A1);
        }
        float a0 = hsum2(A0), a1 = hsum2(A1);
        float rA = fmaf(k2, rcpf_(1.0f + ex2f_(a0)), k3);    // i (A) / g (B)
        float rB = rcpf_(1.0f + ex2f_(a1));                  // f (A) / o (B)
        float gsh = __shfl_sync(FULL, rA, base + 8 + m);     // tanh(g_m) -> half A
        c0v = fmaf(rB, c0v, rA * gsh);                       // valid on half A
        float tc  = tanhf_(c0v);
        float tcs = __shfl_sync(FULL, tc, base + m);         // tanh(c_m) -> half B
        float h0n = rB * tcs;                                // valid on half B

        if (hB) hx[wib][grp][0][m] = h0n;
        __syncwarp();
        {
            ulonglong2 q0 = *(const ulonglong2*)&hx[wib][grp][0][0];
            ulonglong2 q1 = *(const ulonglong2*)&hx[wib][grp][0][4];
            h0p[0] = q0.x; h0p[1] = q0.y; h0p[2] = q1.x; h0p[3] = q1.y;
        }

        // ---- layer 1 ----
        u64 B0 = pk2(b10, 0.f), B1 = pk2(b11, 0.f);
#pragma unroll
        for (int j = 0; j < 4; j++) {
            B0 = ffma2(w1a[j], h0p[j], B0);
            B1 = ffma2(w1b[j], h0p[j], B1);
        }
#pragma unroll
        for (int j = 0; j < 4; j++) {
            B0 = ffma2(w1ha[j], h1p[j], B0);
            B1 = ffma2(w1hb[j], h1p[j], B1);
        }
        float d0 = hsum2(B0), d1 = hsum2(B1);
        float sA = fmaf(k2, rcpf_(1.0f + ex2f_(d0)), k3);
        float sB = rcpf_(1.0f + ex2f_(d1));
        float gsh1 = __shfl_sync(FULL, sA, base + 8 + m);
        c1v = fmaf(sB, c1v, sA * gsh1);
        float tc1  = tanhf_(c1v);
        float tcs1 = __shfl_sync(FULL, tc1, base + m);
        float h1n = sB * tcs1;

        if (hB) hx[wib][grp][1][m] = h1n;
        __syncwarp();
        {
            ulonglong2 q0 = *(const ulonglong2*)&hx[wib][grp][1][0];
            ulonglong2 q1 = *(const ulonglong2*)&hx[wib][grp][1][4];
            h1p[0] = q0.x; h1p[1] = q0.y; h1p[2] = q1.x; h1p[3] = q1.y;
        }

        if (t == len - 1) { yp[0] = h1p[0]; yp[1] = h1p[1]; yp[2] = h1p[2]; yp[3] = h1p[3]; }
        xc = xcn; xd = xdn;
    }

    // ---- heads (once per sequence, lane s==0 holds full y) ----
    if (s == 0) {
        float y[8];
        unpk2(yp[0], y[0], y[1]);
        unpk2(yp[1], y[2], y[3]);
        unpk2(yp[2], y[4], y[5]);
        unpk2(yp[3], y[6], y[7]);

        float feat[4];
#pragma unroll
        for (int j = 0; j < 4; j++) {
            float a = bl[j];
#pragma unroll
            for (int k = 0; k < 8; k++) a = fmaf(Wl[j * 8 + k], y[k], a);
            feat[j] = tanhf_(a);
        }
        float val = bv[0];
#pragma unroll
        for (int j = 0; j < 4; j++) val = fmaf(Wv[j], feat[j], val);
        out[b] = val;
#pragma unroll
        for (int a = 0; a < 4; a++) {
            float mv = ba[a];
#pragma unroll
            for (int j = 0; j < 4; j++) mv = fmaf(Wa[a * 4 + j], feat[j], mv);
            float ls = log_std[a];
            out[BB + b * 4 + a]          = mv;                               // action_mean
            out[BB + 4 * BB + b * 4 + a] = ls;                               // action_log_std
            out[BB + 8 * BB + b * 4 + a] = ex2f_(ls * 1.4426950408889634f);  // action_std
        }
    }
}

extern "C" void kernel_launch(void* const* d_in, const int* in_sizes, int n_in,
                              void* d_out, int out_size)
{
    const float* seq     = (const float*)d_in[0];
    const int*   lengths = (const int*)  d_in[1];
    const float* Wih0 = (const float*)d_in[2];
    const float* Whh0 = (const float*)d_in[3];
    const float* bih0 = (const float*)d_in[4];
    const float* bhh0 = (const float*)d_in[5];
    const float* Wih1 = (const float*)d_in[6];
    const float* Whh1 = (const float*)d_in[7];
    const float* bih1 = (const float*)d_in[8];
    const float* bhh1 = (const float*)d_in[9];
    const float* Wl   = (const float*)d_in[10];
    const float* bl   = (const float*)d_in[11];
    const float* Wv   = (const float*)d_in[12];
    const float* bv   = (const float*)d_in[13];
    const float* Wa   = (const float*)d_in[14];
    const float* ba   = (const float*)d_in[15];
    const float* log_std = (const float*)d_in[16];
    float* out = (float*)d_out;

    // length-descending counting sort -> g_perm
    k_zero<<<(SS + 1023) / 1024, 1024>>>();
    k_hist<<<(BB + 255) / 256, 256>>>(lengths);
    k_scan<<<1, 1024>>>();
    k_scatter<<<(BB + 255) / 256, 256>>>(lengths);

    // main: 2048 warps (2 seqs each), 256 blocks x 256 threads
    lstm_ac_kernel<<<256, 256>>>(seq, lengths,
                                 Wih0, Whh0, bih0, bhh0,
                                 Wih1, Whh1, bih1, bhh1,
                                 Wl, bl, Wv, bv, Wa, ba, log_std,
                                 out);
}